// round 6
// baseline (speedup 1.0000x reference)
#include <cuda_runtime.h>
#include <math.h>

#define BSZ   256
#define ISIZE 256
#define HSIZE 512
#define BH    (BSZ*HSIZE)
#define BK 16

#define BAR_RED(n)  asm volatile("bar.sync 1, %0;" :: "r"(n) : "memory")
#define BAR_GATE(n) asm volatile("bar.sync 2, %0;" :: "r"(n) : "memory")

// Scratch (device globals)
__device__ __align__(16) float g_prex[4*BH];   // x-side gate partials
__device__ __align__(16) float g_preh[4*BH];   // h-side gate partials
__device__ __align__(16) float g_hred[BH];     // sum_h h0*hebb (final)
__device__ __align__(16) float g_ei[BH];       // eta*its per (b,k)

// ---------------------------------------------------------------------------
// K1: warp-specialized. 256 CTAs x 512 threads.
//  warps 0-3  (128 thr): gate GEMM unit bid (phase-split, 64x64 tile)
//  warps 4-15 (384 thr): stream-reduce hred for b = bid (1MB each)
// Sides never interact: separate smem regions, separate named barriers.
// ---------------------------------------------------------------------------
__global__ __launch_bounds__(512, 2)
void k1(const float* __restrict__ x, const float* __restrict__ h0,
        const float* __restrict__ hebb,
        const float* __restrict__ x2f, const float* __restrict__ x2i,
        const float* __restrict__ x2o, const float* __restrict__ x2c,
        const float* __restrict__ h2f, const float* __restrict__ h2i,
        const float* __restrict__ h2o, const float* __restrict__ w)
{
    __shared__ __align__(16) float sh0[HSIZE];       // reduce: h0 row (2KB)
    __shared__ __align__(16) float4 sp[384];         // reduce partials (6KB)
    __shared__ __align__(16) float As[BK][68];       // gates (4.3KB)
    __shared__ __align__(16) float Ws[BK][68];       // gates (4.3KB)

    int tid = threadIdx.x;
    int bid = blockIdx.x;

    if (tid >= 128) {
        // ================= streaming reduce side (384 threads) ============
        int rt = tid - 128;                // 0..383
        int b = bid;
        sh0[rt < 256 ? rt : rt] = h0[b * HSIZE + rt];          // rt in [0,384)
        if (rt < 128) sh0[384 + rt] = h0[b * HSIZE + 384 + rt];
        BAR_RED(384);

        int g = rt >> 7;                   // row-group 0..2 (stride-3 rows)
        int c = rt & 127;                  // f4 column 0..127
        const float4* hb4 = (const float4*)(hebb + (size_t)b * HSIZE * HSIZE) + c;
        float4 acc = make_float4(0.f, 0.f, 0.f, 0.f);
        // h = g, g+3, g+6, ... < 512
#pragma unroll 8
        for (int h = g; h < HSIZE; h += 3) {
            float s = sh0[h];
            float4 v = hb4[(size_t)h * 128];
            acc.x = fmaf(s, v.x, acc.x);
            acc.y = fmaf(s, v.y, acc.y);
            acc.z = fmaf(s, v.z, acc.z);
            acc.w = fmaf(s, v.w, acc.w);
        }
        sp[rt] = acc;
        BAR_RED(384);
        if (g == 0) {
            float4 a = sp[c], b2 = sp[128 + c], d = sp[256 + c];
            a.x += b2.x + d.x;
            a.y += b2.y + d.y;
            a.z += b2.z + d.z;
            a.w += b2.w + d.w;
            ((float4*)(g_hred + b * HSIZE))[c] = a;
        }
        return;
    }

    // ================= gate GEMM side (128 threads) =======================
    // unit = bid: phase = bid>>7 (0=x-side,1=h-side), then gate, tile.
    int phase = bid >> 7;
    int r = bid & 127;
    int gate = r >> 5;
    int ct = r & 31;
    int bn0 = (ct & 7) * 64;               // k offset
    int bm0 = (ct >> 3) * 64;              // b offset
    const float* A = phase ? h0 : x;
    int K = phase ? HSIZE : ISIZE;
    const float* W;
    if (phase == 0)
        W = (gate == 0) ? x2f : (gate == 1) ? x2i : (gate == 2) ? x2o : x2c;
    else
        W = (gate == 0) ? h2f : (gate == 1) ? h2i : (gate == 2) ? h2o : w;
    bool trans = (phase == 1) && (gate == 3);   // w is [h,k]

    int tx = tid & 15;                     // 4 cols each
    int ty = tid >> 4;                     // 0..7, 8 rows each
    float acc[8][4] = {};

    for (int k0 = 0; k0 < K; k0 += BK) {
#pragma unroll
        for (int l = 0; l < 8; l++) {
            int e = tid + l * 128; int rr = e >> 4; int cc = e & 15;
            As[cc][rr] = A[(size_t)(bm0 + rr) * K + k0 + cc];
        }
        if (trans) {
#pragma unroll
            for (int l = 0; l < 8; l++) {
                int e = tid + l * 128; int rr = e & 63; int cc = e >> 6;
                Ws[cc][rr] = W[(size_t)(k0 + cc) * HSIZE + bn0 + rr];
            }
        } else {
#pragma unroll
            for (int l = 0; l < 8; l++) {
                int e = tid + l * 128; int rr = e >> 4; int cc = e & 15;
                Ws[cc][rr] = W[(size_t)(bn0 + rr) * K + k0 + cc];
            }
        }
        BAR_GATE(128);
#pragma unroll
        for (int kb = 0; kb < BK; kb++) {
            float4 ra0 = *(const float4*)&As[kb][ty * 8];
            float4 ra1 = *(const float4*)&As[kb][ty * 8 + 4];
            float4 rb = *(const float4*)&Ws[kb][tx * 4];
            float a[8] = {ra0.x, ra0.y, ra0.z, ra0.w, ra1.x, ra1.y, ra1.z, ra1.w};
            float bv[4] = {rb.x, rb.y, rb.z, rb.w};
#pragma unroll
            for (int i = 0; i < 8; i++)
#pragma unroll
                for (int j = 0; j < 4; j++)
                    acc[i][j] = fmaf(a[i], bv[j], acc[i][j]);
        }
        BAR_GATE(128);
    }
    float* outb = (phase ? g_preh : g_prex) + (size_t)gate * BH;
#pragma unroll
    for (int i = 0; i < 8; i++) {
        int bb = bm0 + ty * 8 + i;
#pragma unroll
        for (int j = 0; j < 4; j++)
            outb[(size_t)bb * HSIZE + bn0 + tx * 4 + j] = acc[i][j];
    }
}

// ---------------------------------------------------------------------------
// K2: per-batch cell/hactiv + modulation scalar + ei = (m*mfw+mfb)*its.
// ---------------------------------------------------------------------------
__global__ __launch_bounds__(HSIZE)
void k2(const float* __restrict__ c0, const float* __restrict__ alpha,
        const float* __restrict__ x2f_b, const float* __restrict__ h2f_b,
        const float* __restrict__ x2i_b, const float* __restrict__ h2i_b,
        const float* __restrict__ x2o_b, const float* __restrict__ h2o_b,
        const float* __restrict__ x2c_b,
        const float* __restrict__ h2mod_w, const float* __restrict__ h2mod_b,
        const float* __restrict__ mfw, const float* __restrict__ mfb,
        float* __restrict__ out_hact, float* __restrict__ out_cell)
{
    __shared__ float sred[16];
    __shared__ float smv;
    int b = blockIdx.x;
    int k = threadIdx.x;
    int idx = b * HSIZE + k;

    float pf = g_prex[idx]          + g_preh[idx]          + x2f_b[k] + h2f_b[k];
    float pi = g_prex[BH + idx]     + g_preh[BH + idx]     + x2i_b[k] + h2i_b[k];
    float po = g_prex[2 * BH + idx] + g_preh[2 * BH + idx] + x2o_b[k] + h2o_b[k];
    float pc = g_prex[3 * BH + idx] + g_preh[3 * BH + idx] + x2c_b[k]
             + alpha[k] * g_hred[idx];
    float fgt = 1.f / (1.f + expf(-pf));
    float ipt = 1.f / (1.f + expf(-pi));
    float opt = 1.f / (1.f + expf(-po));
    float its = tanhf(pc);
    float cell = fgt * c0[idx] + ipt * its;
    float hact = opt * tanhf(cell);
    out_cell[idx] = cell;
    out_hact[idx] = hact;

    float mv = hact * h2mod_w[k];
#pragma unroll
    for (int o = 16; o > 0; o >>= 1) mv += __shfl_down_sync(0xffffffffu, mv, o);
    if ((k & 31) == 0) sred[k >> 5] = mv;
    __syncthreads();
    if (k == 0) {
        float s = 0.f;
#pragma unroll
        for (int i = 0; i < 16; i++) s += sred[i];
        smv = tanhf(s + h2mod_b[0]);
    }
    __syncthreads();
    g_ei[idx] = fmaf(smv, mfw[k], mfb[k]) * its;
}

// ---------------------------------------------------------------------------
// K3: hebb_new[b,h,k] = clip(hebb + h0[b,h]*ei[b,k], -2, 2). Pure streaming.
// ---------------------------------------------------------------------------
__global__ __launch_bounds__(256)
void k3(const float4* __restrict__ hebb4, const float* __restrict__ h0,
        float4* __restrict__ out4)
{
    const float4* ei4 = reinterpret_cast<const float4*>(g_ei);
    int base = blockIdx.x * 1024 + threadIdx.x;
#pragma unroll
    for (int j = 0; j < 4; j++) {
        int idx = base + j * 256;
        int k4 = idx & 127;
        int bh = idx >> 7;
        int b = bh >> 9;
        float s = h0[bh];
        float4 e = ei4[(b << 7) + k4];
        float4 hv = hebb4[idx];
        float v;
        v = fmaf(s, e.x, hv.x); hv.x = fminf(fmaxf(v, -2.f), 2.f);
        v = fmaf(s, e.y, hv.y); hv.y = fminf(fmaxf(v, -2.f), 2.f);
        v = fmaf(s, e.z, hv.z); hv.z = fminf(fmaxf(v, -2.f), 2.f);
        v = fmaf(s, e.w, hv.w); hv.w = fminf(fmaxf(v, -2.f), 2.f);
        out4[idx] = hv;
    }
}

// ---------------------------------------------------------------------------
extern "C" void kernel_launch(void* const* d_in, const int* in_sizes, int n_in,
                              void* d_out, int out_size)
{
    const float* inputs  = (const float*)d_in[0];
    const float* h0      = (const float*)d_in[1];
    const float* c0      = (const float*)d_in[2];
    const float* hebb    = (const float*)d_in[3];
    const float* w       = (const float*)d_in[4];
    const float* alpha   = (const float*)d_in[5];
    const float* h2f_w   = (const float*)d_in[6];
    const float* h2f_b   = (const float*)d_in[7];
    const float* h2i_w   = (const float*)d_in[8];
    const float* h2i_b   = (const float*)d_in[9];
    const float* h2o_w   = (const float*)d_in[10];
    const float* h2o_b   = (const float*)d_in[11];
    const float* x2f_w   = (const float*)d_in[12];
    const float* x2f_b   = (const float*)d_in[13];
    const float* x2i_w   = (const float*)d_in[14];
    const float* x2i_b   = (const float*)d_in[15];
    const float* x2o_w   = (const float*)d_in[16];
    const float* x2o_b   = (const float*)d_in[17];
    const float* x2c_w   = (const float*)d_in[18];
    const float* x2c_b   = (const float*)d_in[19];
    const float* h2mod_w = (const float*)d_in[20];
    const float* h2mod_b = (const float*)d_in[21];
    const float* mfw     = (const float*)d_in[22];
    const float* mfb     = (const float*)d_in[23];

    float* out       = (float*)d_out;
    float* out_hact  = out;              // [B,H]
    float* out_cell  = out + BH;         // [B,H]
    float* out_hebb  = out + 2 * BH;     // [B,H,H]

    // K1: warp-specialized gates + reduce, one CTA per batch row
    k1<<<BSZ, 512>>>(inputs, h0, hebb,
                     x2f_w, x2i_w, x2o_w, x2c_w,
                     h2f_w, h2i_w, h2o_w, w);

    // K2: cell / hactiv / m / ei
    k2<<<BSZ, HSIZE>>>(c0, alpha, x2f_b, h2f_b, x2i_b, h2i_b, x2o_b, h2o_b,
                       x2c_b, h2mod_w, h2mod_b, mfw, mfb, out_hact, out_cell);

    // K3: hebb update (268MB R + 268MB W streaming)
    int nblk = (BSZ * HSIZE * HSIZE / 4) / 1024;   // 8192
    k3<<<nblk, 256>>>((const float4*)hebb, h0, (float4*)out_hebb);
}

// round 7
// speedup vs baseline: 1.1731x; 1.1731x over previous
#include <cuda_runtime.h>
#include <math.h>

#define BSZ   256
#define ISIZE 256
#define HSIZE 512
#define BH    (BSZ*HSIZE)
#define BK 16

#define NGATE 384             // 3 regions (x, hA, hB) x 4 gates x 32 tiles
#define NSLOTS (NGATE + 512)  // + 512 reduce units (b, half)
#define GRID1 296             // 2 CTAs/SM x 148 SMs

// Scratch (device globals)
__device__ __align__(16) float g_prex[4*BH];    // x-side gate partials
__device__ __align__(16) float g_preh0[4*BH];   // h-side partials, K rows 0..255
__device__ __align__(16) float g_preh1[4*BH];   // h-side partials, K rows 256..511
__device__ __align__(16) float g_hredp[8*BH];   // hred partials (2 halves x 4 groups)
__device__ __align__(16) float g_ei[BH];        // eta*its per (b,k)

// ---------------------------------------------------------------------------
// K1: persistent. slots [0,384) = gate GEMM units; [384,896) = reduce units.
// Gate unit: region r in {x, hA, hB}, 64x64 tile, K=256 chunk (16 k-tiles).
// Reduce unit: (b, half) -> 4 row-groups x 64 rows, barrier-free, partials
// to g_hredp. All CTAs do their (1-2) gate units first, then pure streaming.
// ---------------------------------------------------------------------------
__global__ __launch_bounds__(512, 2)
void k1(const float* __restrict__ x, const float* __restrict__ h0,
        const float* __restrict__ hebb,
        const float* __restrict__ x2f, const float* __restrict__ x2i,
        const float* __restrict__ x2o, const float* __restrict__ x2c,
        const float* __restrict__ h2f, const float* __restrict__ h2i,
        const float* __restrict__ h2o, const float* __restrict__ w)
{
    __shared__ __align__(16) float As[BK][68];
    __shared__ __align__(16) float Ws[BK][68];

    int tid = threadIdx.x;

    for (int s = blockIdx.x; s < NSLOTS; s += GRID1) {
        if (s >= NGATE) {
            // ---------------- reduce unit: (b, half), no barriers ----------
            int ru = s - NGATE;
            int b = ru >> 1;
            int half = ru & 1;
            int g = tid >> 7;              // row-group 0..3 (64 rows each)
            int c = tid & 127;             // f4 column
            int hbase = half * 256 + g * 64;
            const float4* hb4 = (const float4*)(hebb + (size_t)b * HSIZE * HSIZE)
                                + (size_t)hbase * 128 + c;
            const float* h0p = h0 + b * HSIZE + hbase;
            float4 acc = make_float4(0.f, 0.f, 0.f, 0.f);
#pragma unroll 8
            for (int i = 0; i < 64; ++i) {
                float sv = __ldg(h0p + i);
                float4 v = hb4[(size_t)i * 128];
                acc.x = fmaf(sv, v.x, acc.x);
                acc.y = fmaf(sv, v.y, acc.y);
                acc.z = fmaf(sv, v.z, acc.z);
                acc.w = fmaf(sv, v.w, acc.w);
            }
            int p = half * 4 + g;          // partial slot 0..7
            ((float4*)(g_hredp + (size_t)p * BH + b * HSIZE))[c] = acc;
        } else {
            // ---------------- gate GEMM unit (16 k-tiles) ------------------
            int region = s >> 7;           // 0=x, 1=h rows 0..255, 2=h rows 256..511
            int r = s & 127;
            int gate = r >> 5;
            int ct = r & 31;
            int bn0 = (ct & 7) * 64;       // k offset
            int bm0 = (ct >> 3) * 64;      // b offset
            const float* A = region ? h0 : x;
            int KA = region ? HSIZE : ISIZE;          // A row stride
            int kbeg = (region == 2) ? 256 : 0;
            const float* W;
            if (region == 0)
                W = (gate == 0) ? x2f : (gate == 1) ? x2i : (gate == 2) ? x2o : x2c;
            else
                W = (gate == 0) ? h2f : (gate == 1) ? h2i : (gate == 2) ? h2o : w;
            bool trans = (region >= 1) && (gate == 3);  // w is [h,k]

            int tx = tid & 15, ty = tid >> 4;           // ty: 0..31
            float acc[2][4] = {};

            for (int kt = 0; kt < 16; ++kt) {
                int k0 = kbeg + kt * BK;
#pragma unroll
                for (int l = 0; l < 2; l++) {
                    int e = tid + l * 512; int rr = e >> 4; int cc = e & 15;
                    As[cc][rr] = A[(size_t)(bm0 + rr) * KA + k0 + cc];
                }
                if (trans) {
#pragma unroll
                    for (int l = 0; l < 2; l++) {
                        int e = tid + l * 512; int rr = e & 63; int cc = e >> 6;
                        Ws[cc][rr] = W[(size_t)(k0 + cc) * HSIZE + bn0 + rr];
                    }
                } else {
#pragma unroll
                    for (int l = 0; l < 2; l++) {
                        int e = tid + l * 512; int rr = e >> 4; int cc = e & 15;
                        Ws[cc][rr] = W[(size_t)(bn0 + rr) * KA + k0 + cc];
                    }
                }
                __syncthreads();
#pragma unroll
                for (int kb = 0; kb < BK; kb++) {
                    float2 ra = *(const float2*)&As[kb][ty * 2];
                    float4 rb = *(const float4*)&Ws[kb][tx * 4];
                    float a[2] = {ra.x, ra.y};
                    float bv[4] = {rb.x, rb.y, rb.z, rb.w};
#pragma unroll
                    for (int i = 0; i < 2; i++)
#pragma unroll
                        for (int j = 0; j < 4; j++)
                            acc[i][j] = fmaf(a[i], bv[j], acc[i][j]);
                }
                __syncthreads();
            }
            float* outb = (region == 0 ? g_prex : region == 1 ? g_preh0 : g_preh1)
                        + (size_t)gate * BH;
#pragma unroll
            for (int i = 0; i < 2; i++) {
                int bb = bm0 + ty * 2 + i;
#pragma unroll
                for (int j = 0; j < 4; j++)
                    outb[(size_t)bb * HSIZE + bn0 + tx * 4 + j] = acc[i][j];
            }
        }
    }
}

// ---------------------------------------------------------------------------
// K2: per-batch cell/hactiv + modulation scalar + ei = (m*mfw+mfb)*its.
// ---------------------------------------------------------------------------
__global__ __launch_bounds__(HSIZE)
void k2(const float* __restrict__ c0, const float* __restrict__ alpha,
        const float* __restrict__ x2f_b, const float* __restrict__ h2f_b,
        const float* __restrict__ x2i_b, const float* __restrict__ h2i_b,
        const float* __restrict__ x2o_b, const float* __restrict__ h2o_b,
        const float* __restrict__ x2c_b,
        const float* __restrict__ h2mod_w, const float* __restrict__ h2mod_b,
        const float* __restrict__ mfw, const float* __restrict__ mfb,
        float* __restrict__ out_hact, float* __restrict__ out_cell)
{
    __shared__ float sred[16];
    __shared__ float smv;
    int b = blockIdx.x;
    int k = threadIdx.x;
    int idx = b * HSIZE + k;

    float hred = 0.f;
#pragma unroll
    for (int p = 0; p < 8; p++) hred += g_hredp[(size_t)p * BH + idx];

    float pf = g_prex[idx]          + g_preh0[idx]          + g_preh1[idx]
             + x2f_b[k] + h2f_b[k];
    float pi = g_prex[BH + idx]     + g_preh0[BH + idx]     + g_preh1[BH + idx]
             + x2i_b[k] + h2i_b[k];
    float po = g_prex[2 * BH + idx] + g_preh0[2 * BH + idx] + g_preh1[2 * BH + idx]
             + x2o_b[k] + h2o_b[k];
    float pc = g_prex[3 * BH + idx] + g_preh0[3 * BH + idx] + g_preh1[3 * BH + idx]
             + x2c_b[k] + alpha[k] * hred;
    float fgt = 1.f / (1.f + expf(-pf));
    float ipt = 1.f / (1.f + expf(-pi));
    float opt = 1.f / (1.f + expf(-po));
    float its = tanhf(pc);
    float cell = fgt * c0[idx] + ipt * its;
    float hact = opt * tanhf(cell);
    out_cell[idx] = cell;
    out_hact[idx] = hact;

    float mv = hact * h2mod_w[k];
#pragma unroll
    for (int o = 16; o > 0; o >>= 1) mv += __shfl_down_sync(0xffffffffu, mv, o);
    if ((k & 31) == 0) sred[k >> 5] = mv;
    __syncthreads();
    if (k == 0) {
        float s = 0.f;
#pragma unroll
        for (int i = 0; i < 16; i++) s += sred[i];
        smv = tanhf(s + h2mod_b[0]);
    }
    __syncthreads();
    g_ei[idx] = fmaf(smv, mfw[k], mfb[k]) * its;
}

// ---------------------------------------------------------------------------
// K3: hebb_new[b,h,k] = clip(hebb + h0[b,h]*ei[b,k], -2, 2). Pure streaming.
// ---------------------------------------------------------------------------
__global__ __launch_bounds__(256)
void k3(const float4* __restrict__ hebb4, const float* __restrict__ h0,
        float4* __restrict__ out4)
{
    const float4* ei4 = reinterpret_cast<const float4*>(g_ei);
    int base = blockIdx.x * 1024 + threadIdx.x;
#pragma unroll
    for (int j = 0; j < 4; j++) {
        int idx = base + j * 256;
        int k4 = idx & 127;
        int bh = idx >> 7;
        int b = bh >> 9;
        float s = h0[bh];
        float4 e = ei4[(b << 7) + k4];
        float4 hv = hebb4[idx];
        float v;
        v = fmaf(s, e.x, hv.x); hv.x = fminf(fmaxf(v, -2.f), 2.f);
        v = fmaf(s, e.y, hv.y); hv.y = fminf(fmaxf(v, -2.f), 2.f);
        v = fmaf(s, e.z, hv.z); hv.z = fminf(fmaxf(v, -2.f), 2.f);
        v = fmaf(s, e.w, hv.w); hv.w = fminf(fmaxf(v, -2.f), 2.f);
        out4[idx] = hv;
    }
}

// ---------------------------------------------------------------------------
extern "C" void kernel_launch(void* const* d_in, const int* in_sizes, int n_in,
                              void* d_out, int out_size)
{
    const float* inputs  = (const float*)d_in[0];
    const float* h0      = (const float*)d_in[1];
    const float* c0      = (const float*)d_in[2];
    const float* hebb    = (const float*)d_in[3];
    const float* w       = (const float*)d_in[4];
    const float* alpha   = (const float*)d_in[5];
    const float* h2f_w   = (const float*)d_in[6];
    const float* h2f_b   = (const float*)d_in[7];
    const float* h2i_w   = (const float*)d_in[8];
    const float* h2i_b   = (const float*)d_in[9];
    const float* h2o_w   = (const float*)d_in[10];
    const float* h2o_b   = (const float*)d_in[11];
    const float* x2f_w   = (const float*)d_in[12];
    const float* x2f_b   = (const float*)d_in[13];
    const float* x2i_w   = (const float*)d_in[14];
    const float* x2i_b   = (const float*)d_in[15];
    const float* x2o_w   = (const float*)d_in[16];
    const float* x2o_b   = (const float*)d_in[17];
    const float* x2c_w   = (const float*)d_in[18];
    const float* x2c_b   = (const float*)d_in[19];
    const float* h2mod_w = (const float*)d_in[20];
    const float* h2mod_b = (const float*)d_in[21];
    const float* mfw     = (const float*)d_in[22];
    const float* mfb     = (const float*)d_in[23];

    float* out       = (float*)d_out;
    float* out_hact  = out;              // [B,H]
    float* out_cell  = out + BH;         // [B,H]
    float* out_hebb  = out + 2 * BH;     // [B,H,H]

    // K1: persistent grid — gates burst first, then barrier-free streaming
    k1<<<GRID1, 512>>>(inputs, h0, hebb,
                       x2f_w, x2i_w, x2o_w, x2c_w,
                       h2f_w, h2i_w, h2o_w, w);

    // K2: cell / hactiv / m / ei
    k2<<<BSZ, HSIZE>>>(c0, alpha, x2f_b, h2f_b, x2i_b, h2i_b, x2o_b, h2o_b,
                       x2c_b, h2mod_w, h2mod_b, mfw, mfb, out_hact, out_cell);

    // K3: hebb update (268MB R + 268MB W streaming)
    int nblk = (BSZ * HSIZE * HSIZE / 4) / 1024;   // 8192
    k3<<<nblk, 256>>>((const float4*)hebb, h0, (float4*)out_hebb);
}